// round 5
// baseline (speedup 1.0000x reference)
#include <cuda_runtime.h>
#include <cuda_bf16.h>

// Problem constants
#define SEQn 256
#define Bn   64
#define Hn   512
#define Ln   4

#define NJ    16      // output columns per block
#define NBC   32      // blocks per (t,l) pair (NBC*NJ == Hn)
#define NTHR  256
#define KC    128     // K-chunk staged in shared

#define WPAD  516     // padded W row stride (floats): %32==4, %4==0 -> conflict-free LDS.128
#define APAD  132     // padded A row stride (floats): %32==4, %4==0 -> conflict-free LDS.128

// Dynamic smem: W tiles [2][NJ][WPAD] + A chunk [Bn][APAD]
#define SMEM_FLOATS (2 * NJ * WPAD + Bn * APAD)
#define SMEM_BYTES  (SMEM_FLOATS * 4)

// Packed dual-fp32 FMA (sm_100+): d = a * w + d, elementwise on {lo,hi}
#define FMA2(d, a, w) \
    asm("fma.rn.f32x2 %0, %1, %2, %3;" : "=l"(d) : "l"(a), "l"(w), "l"(d))

// h(-1) = 0. Never written; device globals are zero-initialized.
__device__ float g_zero[Bn * Hn];

__device__ __forceinline__ float hsum2(unsigned long long v) {
    float lo = __uint_as_float((unsigned int)(v & 0xffffffffull));
    float hi = __uint_as_float((unsigned int)(v >> 32));
    return lo + hi;
}

// One launch per wavefront phase p = t + layer. All (t,layer) pairs on the
// antidiagonal are independent; dependencies live in phase p-1 and are
// enforced by launch ordering. No inter-block synchronization anywhere.
__global__ __launch_bounds__(NTHR, 1)
void rnn_phase_kernel(const float* __restrict__ x,
                      const float* __restrict__ w_ih,
                      const float* __restrict__ b_ih,
                      const float* __restrict__ w_hh,
                      const float* __restrict__ b_hh,
                      float* __restrict__ out,
                      int p, int lmin)
{
    const int layer = lmin + (blockIdx.x >> 5);
    const int t     = p - layer;
    const int cb    = blockIdx.x & (NBC - 1);
    const int j0    = cb * NJ;
    const int tid   = threadIdx.x;

    // Warp/lane tiling: lane = (bl<<2)|jl ; warp = (wj<<2)|wb
    const int lane = tid & 31;
    const int wid  = tid >> 5;
    const int jl   = lane & 3;           // 4 j-lanes (share batch row -> W broadcast)
    const int bl   = lane >> 2;          // 8 b-lanes
    const int wb   = wid & 3;            // 4 b-tiles of 16
    const int wj   = wid >> 2;           // 2 j-tiles of 8

    const int B0 = wb * 16 + bl;         // thread's two batch rows
    const int B1 = B0 + 8;
    const int J0 = wj * 8 + jl;          // thread's two local cols (within NJ)
    const int J1 = J0 + 4;

    extern __shared__ float smem_dyn[];
    float* sW = smem_dyn;                     // [2][NJ][WPAD]: ih then hh
    float* sA = smem_dyn + 2 * NJ * WPAD;     // [Bn][APAD]

    float* outputs = out;                     // [SEQ][B][H]
    float* states  = out + SEQn * Bn * Hn;    // [SEQ][L][B][H]

    const float* inpA = (layer == 0)
        ? (x + (size_t)t * Bn * Hn)
        : (states + (size_t)(t * Ln + (layer - 1)) * Bn * Hn);
    const float* hA = (t == 0)
        ? g_zero
        : (states + (size_t)((t - 1) * Ln + layer) * Bn * Hn);

    // ---- Prologue: batch all weight LDGs (MLP=16, L2-resident), plus the
    // chunk-0 activation prefetch, before any dependent use. ----
    float4 wtmp[16];
    {
        // 2 matrices * NJ rows * 128 float4 per row = 4096 float4; 16/thread
        #pragma unroll
        for (int u = 0; u < 16; ++u) {
            int i  = u * NTHR + tid;
            int m  = i >> 11;                 // 0: ih, 1: hh
            int r  = i & 2047;
            int jj = r >> 7;                  // row within tile
            int q  = r & 127;                 // float4 index within row
            const float* src = (m ? w_hh : w_ih);
            wtmp[u] = ((const float4*)src)[(size_t)(layer * Hn + j0 + jj) * (Hn / 4) + q];
        }
    }

    float pf[32];                             // chunk-0 activation prefetch
    #pragma unroll
    for (int u = 0; u < 32; ++u) {
        int f = u * NTHR + tid;               // 0..8191
        pf[u] = inpA[(f >> 7) * Hn + (f & 127)];
    }

    unsigned long long acc00, acc01, acc10, acc11;
    {
        int jb = layer * Hn + j0;
        float f0 = b_ih[jb + J0] + b_hh[jb + J0];
        float f1 = b_ih[jb + J1] + b_hh[jb + J1];
        acc00 = (unsigned long long)__float_as_uint(f0);   // {bias, 0}
        acc01 = (unsigned long long)__float_as_uint(f1);
        acc10 = acc00;
        acc11 = acc01;
    }

    // Store weights to padded shared tiles (conflict-free STS.128)
    #pragma unroll
    for (int u = 0; u < 16; ++u) {
        int i  = u * NTHR + tid;
        int m  = i >> 11;
        int r  = i & 2047;
        int jj = r >> 7;
        int q  = r & 127;
        *(float4*)(sW + m * NJ * WPAD + jj * WPAD + q * 4) = wtmp[u];
    }
    __syncthreads();

    const float* aR0 = sA + B0 * APAD;
    const float* aR1 = sA + B1 * APAD;

    // 8 K-chunks: 0..3 over inp (Wih), 4..7 over h (Whh)
    for (int cc = 0; cc < 8; ++cc) {
        __syncthreads();      // previous chunk fully consumed
        #pragma unroll
        for (int u = 0; u < 32; ++u) {
            int f = u * NTHR + tid;
            sA[(f >> 7) * APAD + (f & 127)] = pf[u];  // conflict-free STS
        }
        __syncthreads();

        if (cc < 7) {         // prefetch next chunk under this chunk's compute
            const float* Asrc = ((cc + 1) < 4) ? inpA : hA;
            int koff = ((cc + 1) & 3) * KC;
            #pragma unroll
            for (int u = 0; u < 32; ++u) {
                int f = u * NTHR + tid;
                pf[u] = Asrc[(f >> 7) * Hn + koff + (f & 127)];
            }
        }

        const float* wBase = sW + (cc >> 2) * (NJ * WPAD) + (cc & 3) * KC;
        const float* wR0 = wBase + J0 * WPAD;
        const float* wR1 = wBase + J1 * WPAD;

        #pragma unroll 8
        for (int kk = 0; kk < KC; kk += 4) {
            // Each ulonglong2 = two packed f32x2 covering 4 consecutive k.
            ulonglong2 A0 = *(const ulonglong2*)(aR0 + kk);  // 8 addrs/warp, CF
            ulonglong2 A1 = *(const ulonglong2*)(aR1 + kk);
            ulonglong2 W0 = *(const ulonglong2*)(wR0 + kk);  // 4 addrs/warp, CF bcast
            ulonglong2 W1 = *(const ulonglong2*)(wR1 + kk);
            FMA2(acc00, A0.x, W0.x); FMA2(acc00, A0.y, W0.y);
            FMA2(acc01, A0.x, W1.x); FMA2(acc01, A0.y, W1.y);
            FMA2(acc10, A1.x, W0.x); FMA2(acc10, A1.y, W0.y);
            FMA2(acc11, A1.x, W1.x); FMA2(acc11, A1.y, W1.y);
        }
    }

    // Horizontal reduce + activation + writeback
    float r00 = tanhf(hsum2(acc00));
    float r01 = tanhf(hsum2(acc01));
    float r10 = tanhf(hsum2(acc10));
    float r11 = tanhf(hsum2(acc11));
    {
        size_t s0 = ((size_t)(t * Ln + layer) * Bn + B0) * Hn + j0;
        size_t s1 = ((size_t)(t * Ln + layer) * Bn + B1) * Hn + j0;
        states[s0 + J0] = r00;
        states[s0 + J1] = r01;
        states[s1 + J0] = r10;
        states[s1 + J1] = r11;
        if (layer == Ln - 1) {
            size_t o0 = ((size_t)t * Bn + B0) * Hn + j0;
            size_t o1 = ((size_t)t * Bn + B1) * Hn + j0;
            outputs[o0 + J0] = r00;
            outputs[o0 + J1] = r01;
            outputs[o1 + J0] = r10;
            outputs[o1 + J1] = r11;
        }
    }
}

extern "C" void kernel_launch(void* const* d_in, const int* in_sizes, int n_in,
                              void* d_out, int out_size) {
    const float* x    = (const float*)d_in[0];   // [SEQ,B,H]
    const float* w_ih = (const float*)d_in[1];   // [L,H,H]
    const float* b_ih = (const float*)d_in[2];   // [L,H]
    const float* w_hh = (const float*)d_in[3];   // [L,H,H]
    const float* b_hh = (const float*)d_in[4];   // [L,H]
    float* out = (float*)d_out;                  // [SEQ,B,H] outputs ++ [SEQ*L,B,H] states

    cudaFuncSetAttribute(rnn_phase_kernel,
                         cudaFuncAttributeMaxDynamicSharedMemorySize, SMEM_BYTES);

    // Wavefront over launches: phase p = t + layer, p = 0 .. SEQ+L-2.
    // All pairs on an antidiagonal are independent; cross-phase dependencies
    // are enforced by stream/launch order (graph-capture safe, no atomics).
    for (int p = 0; p < SEQn + Ln - 1; ++p) {
        int lmin = (p - (SEQn - 1) > 0) ? (p - (SEQn - 1)) : 0;
        int lmax = (p < Ln - 1) ? p : (Ln - 1);
        int nl   = lmax - lmin + 1;
        rnn_phase_kernel<<<NBC * nl, NTHR, SMEM_BYTES>>>(
            x, w_ih, b_ih, w_hh, b_hh, out, p, lmin);
    }
}